// round 1
// baseline (speedup 1.0000x reference)
#include <cuda_runtime.h>
#include <cstdint>

#define T_STEPS 1024
#define F_IN    64
#define HDIM    40
#define G4      160   // 4*H

// ---------------------------------------------------------------------------
// Fast activations via MUFU (ex2 + rcp). Max error ~1e-6, far below 1e-3 gate.
// ---------------------------------------------------------------------------
__device__ __forceinline__ float sigmoid_f(float x) {
    float e, r;
    asm("ex2.approx.f32 %0, %1;" : "=f"(e) : "f"(-1.4426950408889634f * x));
    asm("rcp.approx.f32 %0, %1;" : "=f"(r) : "f"(1.0f + e));
    return r;
}
__device__ __forceinline__ float tanh_f(float x) {
    // tanh(x) = 1 - 2/(1 + exp(2x));  saturates correctly at +/-inf via ex2/rcp
    float e, r;
    asm("ex2.approx.f32 %0, %1;" : "=f"(e) : "f"(2.8853900817779268f * x));
    asm("rcp.approx.f32 %0, %1;" : "=f"(r) : "f"(1.0f + e));
    return 1.0f - 2.0f * r;
}

__device__ __forceinline__ unsigned smem_u32(const void* p) {
    return (unsigned)__cvta_generic_to_shared(p);
}

// ---------------------------------------------------------------------------
// Fused kernel: one block per batch row.
//   threads [0,160):   LSTM A, thread g computes gate column g
//   threads [160,320): LSTM B, one step behind A (consumes hA_{t-1})
// Weight columns live in registers. seq streamed via cp.async ring (depth 4).
// ---------------------------------------------------------------------------
__global__ void __launch_bounds__(320)
fused_lstm_kernel(
    const float* __restrict__ seq,  const float* __restrict__ feat,
    const float* __restrict__ WaK,  const float* __restrict__ WaR, const float* __restrict__ ba,
    const float* __restrict__ WbK,  const float* __restrict__ WbR, const float* __restrict__ bb,
    const float* __restrict__ Wg,   const float* __restrict__ bg,
    const float* __restrict__ Wh,   const float* __restrict__ bh,
    const float* __restrict__ Wc,   const float* __restrict__ bc,
    const float* __restrict__ Wd,   const float* __restrict__ bd,
    const float* __restrict__ Wo,   const float* __restrict__ bo,
    float* __restrict__ out)
{
    __shared__ __align__(16) float s_seq[8][F_IN];   // cp.async ring, 8 slots
    __shared__ __align__(16) float s_zA[G4];
    __shared__ __align__(16) float s_zB[G4];
    __shared__ __align__(16) float s_hA[HDIM];
    __shared__ __align__(16) float s_hB[HDIM];
    __shared__ float s_t1[10], s_y[10], s_c[20], s_d[10];

    const int tid = threadIdx.x;
    const int b   = blockIdx.x;
    const float* seqb = seq + (size_t)b * T_STEPS * F_IN;

    const bool isA = tid < G4;
    const int  g   = isA ? tid : tid - G4;

    // ---- per-thread weight columns in registers ----
    float wk[F_IN];   // A: 64 used (WaK col). B: 40 used (WbK col).
    float wr[HDIM];   // recurrent col
    float bias;
    if (isA) {
        #pragma unroll
        for (int j = 0; j < F_IN; j++)  wk[j] = WaK[j * G4 + g];
        #pragma unroll
        for (int j = 0; j < HDIM; j++)  wr[j] = WaR[j * G4 + g];
        bias = ba[g];
    } else {
        #pragma unroll
        for (int j = 0; j < HDIM; j++)  wk[j] = WbK[j * G4 + g];
        #pragma unroll
        for (int j = 0; j < HDIM; j++)  wr[j] = WbR[j * G4 + g];
        bias = bb[g];
    }

    if (tid < HDIM) { s_hA[tid] = 0.0f; s_hB[tid] = 0.0f; }
    float c_state = 0.0f;   // cA for tid<40, cB for tid in [160,200)

    // ---- cp.async prologue: steps 0..3 into ring slots 0..3 (4 groups) ----
    if (tid >= 160 && tid < 176) {
        const int k = tid - 160;  // 16 threads x 16B = 256B row
        #pragma unroll
        for (int p = 0; p < 4; p++) {
            unsigned dst = smem_u32(&s_seq[p][k * 4]);
            const float* src = seqb + p * F_IN + k * 4;
            asm volatile("cp.async.ca.shared.global [%0], [%1], 16;\n\t"
                         "cp.async.commit_group;\n" :: "r"(dst), "l"(src));
        }
        asm volatile("cp.async.wait_group 3;");   // slot 0 ready
    }
    __syncthreads();

    // ---- main recurrence: t = 0..1024 (iter 1024 = B's final step only) ----
    for (int t = 0; t <= T_STEPS; t++) {
        // prefetch step t+4 (empty commit group when out of range keeps the
        // wait_group accounting exact)
        if (tid >= 160 && tid < 176) {
            const int k = tid - 160;
            const int tf = t + 4;
            if (tf < T_STEPS) {
                unsigned dst = smem_u32(&s_seq[tf & 7][k * 4]);
                const float* src = seqb + (size_t)tf * F_IN + k * 4;
                asm volatile("cp.async.ca.shared.global [%0], [%1], 16;" :: "r"(dst), "l"(src));
            }
            asm volatile("cp.async.commit_group;");
        }

        // ---- phase 1: gate pre-activations + activation ----
        if (isA) {
            if (t < T_STEPS) {
                const float4* h4 = (const float4*)s_hA;
                const float4* x4 = (const float4*)s_seq[t & 7];
                float a0 = bias, a1 = 0.f, a2 = 0.f, a3 = 0.f;
                #pragma unroll
                for (int j = 0; j < HDIM; j += 4) {
                    float4 h = h4[j >> 2];
                    a0 = fmaf(h.x, wr[j],     a0);
                    a1 = fmaf(h.y, wr[j + 1], a1);
                    a2 = fmaf(h.z, wr[j + 2], a2);
                    a3 = fmaf(h.w, wr[j + 3], a3);
                }
                #pragma unroll
                for (int j = 0; j < F_IN; j += 4) {
                    float4 x = x4[j >> 2];
                    a0 = fmaf(x.x, wk[j],     a0);
                    a1 = fmaf(x.y, wk[j + 1], a1);
                    a2 = fmaf(x.z, wk[j + 2], a2);
                    a3 = fmaf(x.w, wk[j + 3], a3);
                }
                float z = (a0 + a1) + (a2 + a3);
                s_zA[g] = (g >= 2 * HDIM && g < 3 * HDIM) ? tanh_f(z) : sigmoid_f(z);
            }
        } else {
            if (t >= 1) {
                const float4* h4 = (const float4*)s_hB;   // hB_{t-2}
                const float4* x4 = (const float4*)s_hA;   // hA_{t-1} = B's input
                float a0 = bias, a1 = 0.f, a2 = 0.f, a3 = 0.f;
                #pragma unroll
                for (int j = 0; j < HDIM; j += 4) {
                    float4 h = h4[j >> 2];
                    float4 x = x4[j >> 2];
                    a0 = fmaf(h.x, wr[j],     a0);
                    a1 = fmaf(h.y, wr[j + 1], a1);
                    a2 = fmaf(x.x, wk[j],     a2);
                    a3 = fmaf(x.y, wk[j + 1], a3);
                    a0 = fmaf(h.z, wr[j + 2], a0);
                    a1 = fmaf(h.w, wr[j + 3], a1);
                    a2 = fmaf(x.z, wk[j + 2], a2);
                    a3 = fmaf(x.w, wk[j + 3], a3);
                }
                float z = (a0 + a1) + (a2 + a3);
                s_zB[g] = (g >= 2 * HDIM && g < 3 * HDIM) ? tanh_f(z) : sigmoid_f(z);
            }
        }
        __syncthreads();

        // ---- phase 2: cell/state update (i,f,g,o Keras order) ----
        if (isA) {
            if (t < T_STEPS && tid < HDIM) {
                float ai = s_zA[tid], af = s_zA[tid + 40],
                      ag = s_zA[tid + 80], ao = s_zA[tid + 120];
                c_state = af * c_state + ai * ag;
                s_hA[tid] = ao * tanh_f(c_state);
            }
        } else {
            if (t >= 1 && g < HDIM) {
                float ai = s_zB[g], af = s_zB[g + 40],
                      ag = s_zB[g + 80], ao = s_zB[g + 120];
                c_state = af * c_state + ai * ag;
                s_hB[g] = ao * tanh_f(c_state);
            }
            if (tid >= 160 && tid < 176)
                asm volatile("cp.async.wait_group 3;");   // slot t+1 ready
        }
        __syncthreads();
    }

    // ---- dense tail (tiny; s_hB holds x = hB_1023) ----
    const float* fb = feat + (size_t)b * F_IN;
    if (tid < 10) {
        float a = bg[tid];
        #pragma unroll 8
        for (int j = 0; j < F_IN; j++) a = fmaf(fb[j], Wg[j * 10 + tid], a);
        s_t1[tid] = tanh_f(a);
    }
    __syncthreads();
    if (tid < 10) {
        float a = bh[tid];
        #pragma unroll
        for (int j = 0; j < 10; j++) a = fmaf(s_t1[j], Wh[j * 10 + tid], a);
        s_y[tid] = tanh_f(a);
    }
    __syncthreads();
    if (tid < 20) {
        float a = bc[tid];
        #pragma unroll
        for (int j = 0; j < HDIM; j++) a = fmaf(s_hB[j], Wc[j * 20 + tid], a);
        #pragma unroll
        for (int j = 0; j < 10; j++)   a = fmaf(s_y[j], Wc[(HDIM + j) * 20 + tid], a);
        s_c[tid] = fmaxf(a, 0.0f);
    }
    __syncthreads();
    if (tid < 10) {
        float a = bd[tid];
        #pragma unroll
        for (int j = 0; j < 20; j++) a = fmaf(s_c[j], Wd[j * 10 + tid], a);
        s_d[tid] = fmaxf(a, 0.0f);
    }
    __syncthreads();
    if (tid == 0) {
        float a = bo[0];
        #pragma unroll
        for (int j = 0; j < 10; j++) a = fmaf(s_d[j], Wo[j], a);
        out[b] = sigmoid_f(a);
    }
}

// ---------------------------------------------------------------------------
// kernel_launch: inputs in reference-signature order.
// ---------------------------------------------------------------------------
extern "C" void kernel_launch(void* const* d_in, const int* in_sizes, int n_in,
                              void* d_out, int out_size)
{
    (void)in_sizes; (void)n_in; (void)out_size;
    const float* seq  = (const float*)d_in[0];
    const float* feat = (const float*)d_in[1];
    const float* WaK  = (const float*)d_in[2];
    const float* WaR  = (const float*)d_in[3];
    const float* ba   = (const float*)d_in[4];
    const float* WbK  = (const float*)d_in[5];
    const float* WbR  = (const float*)d_in[6];
    const float* bb   = (const float*)d_in[7];
    const float* Wg   = (const float*)d_in[8];
    const float* bg   = (const float*)d_in[9];
    const float* Wh   = (const float*)d_in[10];
    const float* bh   = (const float*)d_in[11];
    const float* Wc   = (const float*)d_in[12];
    const float* bc   = (const float*)d_in[13];
    const float* Wd   = (const float*)d_in[14];
    const float* bd   = (const float*)d_in[15];
    const float* Wo   = (const float*)d_in[16];
    const float* bo   = (const float*)d_in[17];
    float* out = (float*)d_out;

    fused_lstm_kernel<<<512, 320>>>(seq, feat, WaK, WaR, ba, WbK, WbR, bb,
                                    Wg, bg, Wh, bh, Wc, bc, Wd, bd, Wo, bo, out);
}

// round 3
// speedup vs baseline: 1.5817x; 1.5817x over previous
#include <cuda_runtime.h>
#include <cstdint>

#define T_STEPS 1024
#define F_IN    64
#define HDIM    40
#define G4      160   // 4*H
#define R       4     // batch rows per block

typedef unsigned long long ull;

// ---------------------------------------------------------------------------
// Packed f32x2 helpers (Blackwell packed fp32 FMA)
// ---------------------------------------------------------------------------
__device__ __forceinline__ ull pack2(float a, float b) {
    ull r; asm("mov.b64 %0, {%1,%2};" : "=l"(r) : "f"(a), "f"(b)); return r;
}
__device__ __forceinline__ void unpack2(ull v, float& a, float& b) {
    asm("mov.b64 {%0,%1}, %2;" : "=f"(a), "=f"(b) : "l"(v));
}
__device__ __forceinline__ void ffma2(ull& d, ull a, ull b) {
    asm("fma.rn.f32x2 %0, %1, %2, %0;" : "+l"(d) : "l"(a), "l"(b));
}

// ---------------------------------------------------------------------------
// Fast activations via MUFU (ex2 + rcp). Max error ~1e-6.
// ---------------------------------------------------------------------------
__device__ __forceinline__ float sigmoid_f(float x) {
    float e, r;
    asm("ex2.approx.f32 %0, %1;" : "=f"(e) : "f"(-1.4426950408889634f * x));
    asm("rcp.approx.f32 %0, %1;" : "=f"(r) : "f"(1.0f + e));
    return r;
}
__device__ __forceinline__ float tanh_f(float x) {
    float e, r;
    asm("ex2.approx.f32 %0, %1;" : "=f"(e) : "f"(2.8853900817779268f * x));
    asm("rcp.approx.f32 %0, %1;" : "=f"(r) : "f"(1.0f + e));
    return 1.0f - 2.0f * r;
}

__device__ __forceinline__ unsigned smem_u32(const void* p) {
    return (unsigned)__cvta_generic_to_shared(p);
}

// ---------------------------------------------------------------------------
// Fused kernel: one block per 4 batch rows (grid 128 = single wave).
//   threads [0,160):   LSTM A, thread g computes gate column g for all 4 rows
//   threads [160,320): LSTM B, one step behind A
// Weight columns live in registers as j-packed f32x2 pairs. seq streamed via
// cp.async ring (depth 4, row-major so packed pairs come free from LDS.128).
// ---------------------------------------------------------------------------
__global__ void __launch_bounds__(320)
fused_lstm_kernel(
    const float* __restrict__ seq,  const float* __restrict__ feat,
    const float* __restrict__ WaK,  const float* __restrict__ WaR, const float* __restrict__ ba,
    const float* __restrict__ WbK,  const float* __restrict__ WbR, const float* __restrict__ bb,
    const float* __restrict__ Wg,   const float* __restrict__ bg,
    const float* __restrict__ Wh,   const float* __restrict__ bh,
    const float* __restrict__ Wc,   const float* __restrict__ bc,
    const float* __restrict__ Wd,   const float* __restrict__ bd,
    const float* __restrict__ Wo,   const float* __restrict__ bo,
    float* __restrict__ out)
{
    __shared__ __align__(16) float s_seq[8][R][F_IN];   // cp.async ring
    __shared__ __align__(16) float s_zA[R][G4];
    __shared__ __align__(16) float s_zB[R][G4];
    __shared__ __align__(16) float s_hA[R][HDIM];
    __shared__ __align__(16) float s_hB[R][HDIM];
    __shared__ float s_t1[R][10], s_y[R][10], s_c[R][20], s_d[R][10];

    const int tid = threadIdx.x;
    const int b4  = blockIdx.x * R;

    const bool isA = tid < G4;
    const int  g   = isA ? tid : tid - G4;
    const bool isTanhGate = (g >= 2 * HDIM && g < 3 * HDIM);

    // phase-2 (state-update) mapping: each thread owns one (row, h-index)
    const int p2idx = isA ? tid : tid - G4;
    const int r2 = p2idx / HDIM;       // 0..3
    const int j2 = p2idx % HDIM;       // 0..39

    // ---- per-thread weight columns in registers, j-packed as f32x2 ----
    ull wk2[32];   // A: 32 pairs (F=64). B: 20 pairs (H=40) used.
    ull wr2[20];   // recurrent: 20 pairs (H=40)
    float bias;
    if (isA) {
        #pragma unroll
        for (int m = 0; m < 32; m++)
            wk2[m] = pack2(WaK[(2 * m) * G4 + g], WaK[(2 * m + 1) * G4 + g]);
        #pragma unroll
        for (int m = 0; m < 20; m++)
            wr2[m] = pack2(WaR[(2 * m) * G4 + g], WaR[(2 * m + 1) * G4 + g]);
        bias = ba[g];
    } else {
        #pragma unroll
        for (int m = 0; m < 20; m++)
            wk2[m] = pack2(WbK[(2 * m) * G4 + g], WbK[(2 * m + 1) * G4 + g]);
        #pragma unroll
        for (int m = 0; m < 20; m++)
            wr2[m] = pack2(WbR[(2 * m) * G4 + g], WbR[(2 * m + 1) * G4 + g]);
        bias = bb[g];
    }

    if (tid < R * HDIM) s_hA[tid / HDIM][tid % HDIM] = 0.0f;
    else if (tid >= G4 && tid < G4 + R * HDIM) s_hB[r2][j2] = 0.0f;
    float c_state = 0.0f;   // cA for A threads, cB for B threads (one (r,j) each)

    // ---- cp.async prologue: steps 0..3 into ring slots 0..3 (4 groups) ----
    if (tid >= 160 && tid < 224) {
        const int k = tid - 160, row = k >> 4, lane = k & 15;
        const float* srcb = seq + ((size_t)(b4 + row) * T_STEPS) * F_IN + lane * 4;
        #pragma unroll
        for (int p = 0; p < 4; p++) {
            unsigned dst = smem_u32(&s_seq[p][row][lane * 4]);
            asm volatile("cp.async.ca.shared.global [%0], [%1], 16;\n\t"
                         "cp.async.commit_group;\n" :: "r"(dst), "l"(srcb + (size_t)p * F_IN));
        }
        asm volatile("cp.async.wait_group 3;");   // slot 0 ready
    }
    __syncthreads();

    // ---- main recurrence ----
    for (int t = 0; t <= T_STEPS; t++) {
        // prefetch step t+4 (empty commit group keeps wait accounting exact)
        if (tid >= 160 && tid < 224) {
            const int k = tid - 160, row = k >> 4, lane = k & 15;
            const int tf = t + 4;
            if (tf < T_STEPS) {
                unsigned dst = smem_u32(&s_seq[tf & 7][row][lane * 4]);
                const float* src = seq + ((size_t)(b4 + row) * T_STEPS + tf) * F_IN + lane * 4;
                asm volatile("cp.async.ca.shared.global [%0], [%1], 16;" :: "r"(dst), "l"(src));
            }
            asm volatile("cp.async.commit_group;");
        }

        // ---- phase 1: gate pre-activations for all 4 rows ----
        if (isA) {
            if (t < T_STEPS) {
                #pragma unroll
                for (int r = 0; r < R; r++) {
                    const ulonglong2* x2 = (const ulonglong2*)(&s_seq[t & 7][r][0]);
                    const ulonglong2* h2 = (const ulonglong2*)(&s_hA[r][0]);
                    ull a0 = 0, a1 = 0;
                    #pragma unroll
                    for (int q = 0; q < 16; q++) {
                        ulonglong2 v = x2[q];
                        ffma2(a0, wk2[2 * q],     v.x);
                        ffma2(a1, wk2[2 * q + 1], v.y);
                    }
                    #pragma unroll
                    for (int q = 0; q < 10; q++) {
                        ulonglong2 v = h2[q];
                        ffma2(a0, wr2[2 * q],     v.x);
                        ffma2(a1, wr2[2 * q + 1], v.y);
                    }
                    float p0, p1, p2, p3;
                    unpack2(a0, p0, p1); unpack2(a1, p2, p3);
                    float z = bias + ((p0 + p2) + (p1 + p3));
                    s_zA[r][g] = isTanhGate ? tanh_f(z) : sigmoid_f(z);
                }
            }
        } else {
            if (t >= 1) {
                #pragma unroll
                for (int r = 0; r < R; r++) {
                    const ulonglong2* x2 = (const ulonglong2*)(&s_hA[r][0]);  // hA_{t-1}
                    const ulonglong2* h2 = (const ulonglong2*)(&s_hB[r][0]);  // hB_{t-2}
                    ull a0 = 0, a1 = 0;
                    #pragma unroll
                    for (int q = 0; q < 10; q++) {
                        ulonglong2 vx = x2[q];
                        ulonglong2 vh = h2[q];
                        ffma2(a0, wk2[2 * q],     vx.x);
                        ffma2(a1, wk2[2 * q + 1], vx.y);
                        ffma2(a0, wr2[2 * q],     vh.x);
                        ffma2(a1, wr2[2 * q + 1], vh.y);
                    }
                    float p0, p1, p2, p3;
                    unpack2(a0, p0, p1); unpack2(a1, p2, p3);
                    float z = bias + ((p0 + p2) + (p1 + p3));
                    s_zB[r][g] = isTanhGate ? tanh_f(z) : sigmoid_f(z);
                }
            }
        }
        __syncthreads();

        // ---- phase 2: cell/state update, one (row, j) per thread ----
        if (isA) {
            if (t < T_STEPS) {
                float zi = s_zA[r2][j2],      zf = s_zA[r2][j2 + 40],
                      zg = s_zA[r2][j2 + 80], zo = s_zA[r2][j2 + 120];
                c_state = zf * c_state + zi * zg;
                s_hA[r2][j2] = zo * tanh_f(c_state);
            }
        } else {
            if (t >= 1) {
                float zi = s_zB[r2][j2],      zf = s_zB[r2][j2 + 40],
                      zg = s_zB[r2][j2 + 80], zo = s_zB[r2][j2 + 120];
                c_state = zf * c_state + zi * zg;
                s_hB[r2][j2] = zo * tanh_f(c_state);
            }
            if (tid >= 160 && tid < 224)
                asm volatile("cp.async.wait_group 3;");   // slot t+1 ready
        }
        __syncthreads();
    }

    // ---- dense tail: threads [0,160) = (r, u) with r=tid/40, u=tid%40 ----
    {
        const int r = r2, u = j2;
        const bool act = isA;
        const float* fb = feat + (size_t)(b4 + r) * F_IN;
        if (act && u < 10) {
            float a = bg[u];
            #pragma unroll 8
            for (int j = 0; j < F_IN; j++) a = fmaf(fb[j], Wg[j * 10 + u], a);
            s_t1[r][u] = tanh_f(a);
        }
        __syncthreads();
        if (act && u < 10) {
            float a = bh[u];
            #pragma unroll
            for (int j = 0; j < 10; j++) a = fmaf(s_t1[r][j], Wh[j * 10 + u], a);
            s_y[r][u] = tanh_f(a);
        }
        __syncthreads();
        if (act && u < 20) {
            float a = bc[u];
            #pragma unroll
            for (int j = 0; j < HDIM; j++) a = fmaf(s_hB[r][j], Wc[j * 20 + u], a);
            #pragma unroll
            for (int j = 0; j < 10; j++)   a = fmaf(s_y[r][j], Wc[(HDIM + j) * 20 + u], a);
            s_c[r][u] = fmaxf(a, 0.0f);
        }
        __syncthreads();
        if (act && u < 10) {
            float a = bd[u];
            #pragma unroll
            for (int j = 0; j < 20; j++) a = fmaf(s_c[r][j], Wd[j * 10 + u], a);
            s_d[r][u] = fmaxf(a, 0.0f);
        }
        __syncthreads();
        if (act && u == 0) {
            float a = bo[0];
            #pragma unroll
            for (int j = 0; j < 10; j++) a = fmaf(s_d[r][j], Wo[j], a);
            out[b4 + r] = sigmoid_f(a);
        }
    }
}

// ---------------------------------------------------------------------------
extern "C" void kernel_launch(void* const* d_in, const int* in_sizes, int n_in,
                              void* d_out, int out_size)
{
    (void)in_sizes; (void)n_in; (void)out_size;
    const float* seq  = (const float*)d_in[0];
    const float* feat = (const float*)d_in[1];
    const float* WaK  = (const float*)d_in[2];
    const float* WaR  = (const float*)d_in[3];
    const float* ba   = (const float*)d_in[4];
    const float* WbK  = (const float*)d_in[5];
    const float* WbR  = (const float*)d_in[6];
    const float* bb   = (const float*)d_in[7];
    const float* Wg   = (const float*)d_in[8];
    const float* bg   = (const float*)d_in[9];
    const float* Wh   = (const float*)d_in[10];
    const float* bh   = (const float*)d_in[11];
    const float* Wc   = (const float*)d_in[12];
    const float* bc   = (const float*)d_in[13];
    const float* Wd   = (const float*)d_in[14];
    const float* bd   = (const float*)d_in[15];
    const float* Wo   = (const float*)d_in[16];
    const float* bo   = (const float*)d_in[17];
    float* out = (float*)d_out;

    fused_lstm_kernel<<<512 / R, 320>>>(seq, feat, WaK, WaR, ba, WbK, WbR, bb,
                                        Wg, bg, Wh, bh, Wc, bc, Wd, bd, Wo, bo, out);
}